// round 12
// baseline (speedup 1.0000x reference)
#include <cuda_runtime.h>
#include <cuda_bf16.h>
#include <math.h>
#include <stdint.h>

#define NBATCH 16
#define NEDGE  131072
#define NN1    8192
#define KP1    410
#define KP2    205
#define NN2    6560      /* 16*410 */
#define EMB    512
#define F3     1536
#define E1TOT  (NEDGE+NN1)
#define E2TOT  (NEDGE+NN2)
#define NCH1   52        /* CDIV(KP1,8) */
#define NCH2   26        /* CDIV(KP2,8) */
#define DCAP   128       /* padded-CSR per-node capacity (max in-degree ~45) */
#define CDIV(a,b) (((a)+(b)-1)/(b))

/* tcgen05 availability: only in arch-specific device passes. */
#if !defined(__CUDA_ARCH__) || defined(__CUDA_ARCH_FEAT_SM103_ALL) || \
    defined(__CUDA_ARCH_FEAT_SM100_ALL) || defined(__CUDA_ARCH_SPECIFIC__) || \
    defined(__CUDA_ARCH_FAMILY_SPECIFIC__)
#define TG_TC 1
#else
#define TG_TC 0
#endif

/* ================= PTX helpers ================= */
__device__ __forceinline__ uint32_t smem_u32(const void* p){
    uint32_t a;
    asm("{ .reg .u64 t; cvta.to.shared.u64 t, %1; cvt.u32.u64 %0, t; }" : "=r"(a) : "l"(p));
    return a;
}
#define TCGEN05_ALLOC(sa, n) \
    asm volatile("tcgen05.alloc.cta_group::1.sync.aligned.shared::cta.b32 [%0], %1;" \
        :: "r"((uint32_t)(sa)), "r"((uint32_t)(n)) : "memory")
#define TCGEN05_DEALLOC(tm, n) \
    asm volatile("tcgen05.dealloc.cta_group::1.sync.aligned.b32 %0, %1;" :: "r"(tm), "r"((uint32_t)(n)))
#define TCGEN05_RELINQ() \
    asm volatile("tcgen05.relinquish_alloc_permit.cta_group::1.sync.aligned;")
#define TCGEN05_COMMIT_MC(mb, mask) \
    asm volatile("tcgen05.commit.cta_group::1.mbarrier::arrive::one.shared::cluster.multicast::cluster.b64 [%0], %1;" \
        :: "r"((uint32_t)(mb)), "h"((uint16_t)(mask)) : "memory")
#define TCGEN05_FENCE_AFTER()  asm volatile("tcgen05.fence::after_thread_sync;" ::: "memory")
#define TCGEN05_FENCE_BEFORE() asm volatile("tcgen05.fence::before_thread_sync;" ::: "memory")
#define TCGEN05_WAIT_LD()      asm volatile("tcgen05.wait::ld.sync.aligned;" ::: "memory")
#define MBARRIER_INIT(mb, c) \
    asm volatile("mbarrier.init.shared.b64 [%0], %1;" :: "r"((uint32_t)(mb)), "r"((uint32_t)(c)) : "memory")
#define MBARRIER_EXPECT_TX(mb, n) \
    asm volatile("mbarrier.arrive.expect_tx.shared.b64 _, [%0], %1;" \
        :: "r"((uint32_t)(mb)), "r"((uint32_t)(n)) : "memory")
#define MBARRIER_WAIT_PARITY(mb, ph) do { \
    uint32_t _m = (uint32_t)(mb), _p = (uint32_t)(ph), _d; \
    asm volatile("{\n\t.reg .pred p;\n\t" \
        "mbarrier.try_wait.parity.acquire.cta.shared::cta.b64 p, [%1], %2;\n\t" \
        "selp.b32 %0, 1, 0, p;\n\t}" : "=r"(_d) : "r"(_m), "r"(_p) : "memory"); \
    if(!_d){ \
        asm volatile("{\n\t.reg .pred P1;\n\t" \
            "WL_%=:\n\t" \
            "mbarrier.try_wait.parity.acquire.cta.shared::cta.b64 P1, [%0], %1, 0x989680;\n\t" \
            "@P1 bra.uni WD_%=;\n\t" \
            "bra.uni WL_%=;\n\t" \
            "WD_%=:\n\t}" :: "r"(_m), "r"(_p) : "memory"); \
    } } while(0)
#define BULK_G2S_MC(dst, src, sz, mb, mask) \
    asm volatile("cp.async.bulk.shared::cluster.global.mbarrier::complete_tx::bytes.multicast::cluster [%0], [%1], %2, [%3], %4;" \
        :: "r"((uint32_t)(dst)), "l"(src), "r"((uint32_t)(sz)), "r"((uint32_t)(mb)), \
           "h"((uint16_t)(mask)) : "memory")
#define CLUSTER_SYNC() do { \
    asm volatile("barrier.cluster.arrive.aligned;" ::: "memory"); \
    asm volatile("barrier.cluster.wait.aligned;" ::: "memory"); } while(0)
#define TCGEN05_LD_X32(r, ta) \
    asm volatile("tcgen05.ld.sync.aligned.32x32b.x32.b32 " \
        "{%0, %1, %2, %3, %4, %5, %6, %7, %8, %9, %10, %11, %12, %13, %14, %15, " \
        " %16, %17, %18, %19, %20, %21, %22, %23, %24, %25, %26, %27, %28, %29, %30, %31}, [%32];" \
        : "=r"((r)[0]),  "=r"((r)[1]),  "=r"((r)[2]),  "=r"((r)[3]), \
          "=r"((r)[4]),  "=r"((r)[5]),  "=r"((r)[6]),  "=r"((r)[7]), \
          "=r"((r)[8]),  "=r"((r)[9]),  "=r"((r)[10]), "=r"((r)[11]), \
          "=r"((r)[12]), "=r"((r)[13]), "=r"((r)[14]), "=r"((r)[15]), \
          "=r"((r)[16]), "=r"((r)[17]), "=r"((r)[18]), "=r"((r)[19]), \
          "=r"((r)[20]), "=r"((r)[21]), "=r"((r)[22]), "=r"((r)[23]), \
          "=r"((r)[24]), "=r"((r)[25]), "=r"((r)[26]), "=r"((r)[27]), \
          "=r"((r)[28]), "=r"((r)[29]), "=r"((r)[30]), "=r"((r)[31]) \
        : "r"(ta))
#if TG_TC
__device__ __forceinline__ void mma_f16_ss(uint32_t d, uint64_t a, uint64_t b,
                                           uint32_t idesc, uint32_t acc){
    uint32_t z = 0;
    asm volatile("{\n\t.reg .pred p;\n\tsetp.ne.u32 p, %5, 0;\n\t"
        "tcgen05.mma.cta_group::1.kind::f16 [%0], %1, %2, %3, {%4, %4, %4, %4}, p;\n\t}"
        :: "r"(d), "l"(a), "l"(b), "r"(idesc), "r"(z), "r"(acc) : "memory");
}
#endif
static __device__ __forceinline__ uint64_t mk_desc(uint32_t base){
    const uint64_t B = (uint64_t(2) << 61) | (uint64_t(1) << 46)
                     | (uint64_t(64) << 32) | (uint64_t(1) << 16);
    return B | ((uint64_t)(base >> 4) & 0x3FFF);
}

/* byte offset of bf16 element (row, k3) in tile-chunk-major pre-swizzled layout */
__device__ __forceinline__ size_t swaddr(int row, int k3, int K3){
    int nchunk = K3 >> 6;
    int mb = row >> 7, r = row & 127;
    int kb = k3 << 1;
    int c = kb >> 7, q = kb & 127;
    int blk = (q >> 4) ^ (r & 7);
    return ((((size_t)mb*nchunk + c)*128 + r) << 7) + (blk << 4) + (q & 15);
}
__device__ __forceinline__ uint16_t bfbits(__nv_bfloat16 h){
    return *reinterpret_cast<uint16_t*>(&h);
}

/* ---------------- scratch ---------------- */
__device__ __align__(16) float d_xp1 [NN1*F3];
__device__ float    d_asn1[NN1*3], d_adn1[NN1*3];
__device__ unsigned d_emax1[NN1*3];
__device__ int      d_cnt1[NN1], d_eid1[NN1*DCAP];
__device__ float    d_h1  [NN1*EMB];
__device__ float    d_y1  [NN1*EMB];
__device__ float    d_sc1 [NN1];
__device__ int      d_map1[NN1];
__device__ int      d_s2  [NEDGE], d_t2[NEDGE];

__device__ __align__(16) float d_xp2 [NN2*F3];
__device__ float    d_asn2[NN2*3], d_adn2[NN2*3];
__device__ unsigned d_emax2[NN2*3];
__device__ int      d_cnt2[NN2], d_eid2[NN2*DCAP];
__device__ float    d_h2  [NN2*EMB];
__device__ float    d_y2  [NN2*EMB];
__device__ float    d_sc2 [NN2];

__device__ float    d_bsum1[EMB], d_bsq1[EMB], d_bsum2[EMB], d_bsq2[EMB];
__device__ float    d_rnorm[2];

/* top-k staging + pool partials */
__device__ int      d_prm [NBATCH*512];
__device__ float    d_psc [NBATCH*512];
__device__ float    d_pm1 [NBATCH*NCH1*512], d_ps1[NBATCH*NCH1*512];
__device__ float    d_pm2 [NBATCH*NCH2*512], d_ps2[NBATCH*NCH2*512];

/* bf16 split buffers (tile-chunk-major pre-swizzled) */
__device__ __align__(128) __nv_bfloat16 d_a16 [(size_t)NN1*3*F3];
__device__ __align__(128) __nv_bfloat16 d_bw1 [512*3*F3];
__device__ __align__(128) __nv_bfloat16 d_bw2 [F3*3*EMB];
__device__ __align__(128) __nv_bfloat16 d_bw3 [512*3*F3];

/* ------------------------------- helpers ---------------------------------- */
__device__ __forceinline__ unsigned f2o(float f){
    unsigned u = __float_as_uint(f);
    return (u & 0x80000000u) ? ~u : (u | 0x80000000u);
}
__device__ __forceinline__ float o2f(unsigned e){
    return (e & 0x80000000u) ? __uint_as_float(e & 0x7FFFFFFFu)
                             : __uint_as_float(~e);
}
__device__ __forceinline__ void split2(float v, __nv_bfloat16& hi, __nv_bfloat16& lo){
    hi = __float2bfloat16(v);
    lo = __float2bfloat16(v - __bfloat162float(hi));
}

__global__ void k_zero_all(){
    int i = blockIdx.x*blockDim.x + threadIdx.x;
    if(i < NN1*3){ d_emax1[i] = 0u; }
    if(i < NN1){ d_cnt1[i] = 0; }
    if(i < NN2*3){ d_emax2[i] = 0u; }
    if(i < NN2){ d_cnt2[i] = 0; }
    if(i < EMB){ d_bsum1[i]=0.f; d_bsq1[i]=0.f; d_bsum2[i]=0.f; d_bsq2[i]=0.f; }
}

/* W[K,N] -> B'[n][3K]=[hi|hi|lo] in tile-chunk-major pre-swizzled layout */
__global__ void k_split_bT(const float* __restrict__ W, __nv_bfloat16* __restrict__ O,
                           int K, int N){
    __shared__ float tile[32][33];
    int k0 = blockIdx.x*32, n0 = blockIdx.y*32;
    int tx = threadIdx.x, ty = threadIdx.y;
    int K3 = 3*K;
    char* Ob = (char*)O;
    #pragma unroll
    for(int i = ty; i < 32; i += 8)
        tile[i][tx] = W[(size_t)(k0+i)*N + n0 + tx];
    __syncthreads();
    #pragma unroll
    for(int i = ty; i < 32; i += 8){
        int n = n0 + i, k = k0 + tx;
        float w = tile[tx][i];
        __nv_bfloat16 hi, lo; split2(w, hi, lo);
        *(__nv_bfloat16*)(Ob + swaddr(n, k,       K3)) = hi;
        *(__nv_bfloat16*)(Ob + swaddr(n, K + k,   K3)) = hi;
        *(__nv_bfloat16*)(Ob + swaddr(n, 2*K + k, K3)) = lo;
    }
}

/* fused: xp1 = x@W1 and attention dots. one block (256 thr) per node */
__global__ void k_xw1att(const float* __restrict__ x, const float* __restrict__ W,
                         const float* __restrict__ as_, const float* __restrict__ ad_){
    int n = blockIdx.x, t = threadIdx.x;
    float x0 = x[n*3], x1 = x[n*3+1], x2 = x[n*3+2];
    float sa[3] = {0,0,0}, da[3] = {0,0,0};
    #pragma unroll
    for(int u = 0; u < 6; u++){
        int j = t + u*256;
        float v = x0*W[j] + x1*W[F3+j] + x2*W[2*F3+j];
        d_xp1[(size_t)n*F3 + j] = v;
        sa[u>>1] += v*as_[j]; da[u>>1] += v*ad_[j];
    }
    __shared__ float R[6*256];
    #pragma unroll
    for(int h = 0; h < 3; h++){ R[h*256+t] = sa[h]; R[(3+h)*256+t] = da[h]; }
    __syncthreads();
    for(int off = 128; off; off >>= 1){
        if(t < off){
            #pragma unroll
            for(int ch = 0; ch < 6; ch++) R[ch*256+t] += R[ch*256+t+off];
        }
        __syncthreads();
    }
    if(t < 3) d_asn1[n*3+t] = R[t*256];
    else if(t < 6) d_adn1[n*3 + (t-3)] = R[t*256];
}

/* warp-specialized tcgen05 bf16 SS GEMM, 2x2 cluster with A/B bulk-multicast.
   A shared across the cluster-x pair, B across the cluster-y pair. */
#define TG_STAGES 3
#define TG_THREADS 192
#define TG_SMEM (1024 + TG_STAGES*32768)
template<int RELU>
__global__ __launch_bounds__(TG_THREADS) __cluster_dims__(2,2,1)
void k_tgemm(const __nv_bfloat16* __restrict__ A, const __nv_bfloat16* __restrict__ Bw,
             const float* __restrict__ bias, float* __restrict__ C,
             int M, int N, int K3){
#if TG_TC
    extern __shared__ char smem[];
    uint32_t sb = smem_u32(smem);
    int tid = threadIdx.x, wid = tid >> 5, lane = tid & 31;
    int bm = blockIdx.y*128, bn = blockIdx.x*128;
    int nchunk = K3 >> 6;
    int cx = blockIdx.x & 1, cy = blockIdx.y & 1;
    uint16_t amask = (uint16_t)(0x3u << (2*cy));     /* x-pair, same M */
    uint16_t bmask = (uint16_t)(0x5u << cx);         /* y-pair, same N */

    if(wid == 0){ TCGEN05_ALLOC(sb, 128); TCGEN05_RELINQ(); }
    if(tid == 0){
        #pragma unroll
        for(int s = 0; s < TG_STAGES; s++){
            MBARRIER_INIT(sb + 8 + 8*s, 1);     /* full[s]: one expect-arrive */
            MBARRIER_INIT(sb + 40 + 8*s, 4);    /* empty[s]: 4 MMA commits (cluster) */
        }
    }
    __syncthreads();
    CLUSTER_SYNC();
    uint32_t tmem;
    asm volatile("ld.shared.b32 %0, [%1];" : "=r"(tmem) : "r"(sb));

    if(wid == 4 && lane == 0){
        const char* abase = (const char*)A + ((size_t)(bm >> 7)*nchunk << 14);
        const char* bbase = (const char*)Bw + ((size_t)(bn >> 7)*nchunk << 14);
        for(int kc = 0; kc < nchunk; kc++){
            int b = kc % TG_STAGES, r = kc / TG_STAGES;
            if(r > 0) MBARRIER_WAIT_PARITY(sb + 40 + 8*b, (r-1) & 1);
            uint32_t st = sb + 1024 + b*32768;
            MBARRIER_EXPECT_TX(sb + 8 + 8*b, 32768);
            if(cx == 0) BULK_G2S_MC(st,         abase + ((size_t)kc << 14), 16384, sb + 8 + 8*b, amask);
            if(cy == 0) BULK_G2S_MC(st + 16384, bbase + ((size_t)kc << 14), 16384, sb + 8 + 8*b, bmask);
        }
    }
    if(wid == 5 && lane == 0){
        const uint32_t idesc = (1u<<4)|(1u<<7)|(1u<<10)|(16u<<17)|(8u<<24);
        for(int kc = 0; kc < nchunk; kc++){
            int b = kc % TG_STAGES, r = kc / TG_STAGES;
            MBARRIER_WAIT_PARITY(sb + 8 + 8*b, r & 1);
            uint64_t ad = mk_desc(sb + 1024 + b*32768);
            uint64_t bd = mk_desc(sb + 1024 + b*32768 + 16384);
            #pragma unroll
            for(int k = 0; k < 4; k++)
                mma_f16_ss(tmem, ad + k*2, bd + k*2, idesc, (kc > 0) | (k > 0));
            TCGEN05_COMMIT_MC(sb + 40 + 8*b, 0xF);
        }
        int kl = nchunk - 1;
        MBARRIER_WAIT_PARITY(sb + 40 + 8*(kl % TG_STAGES), (kl / TG_STAGES) & 1);
    }
    __syncthreads();
    TCGEN05_FENCE_AFTER();

    if(wid < 4){
        int row = bm + wid*32 + lane;
        #pragma unroll
        for(int c0 = 0; c0 < 128; c0 += 32){
            uint32_t d[32];
            TCGEN05_LD_X32(d, tmem + c0);
            TCGEN05_WAIT_LD();
            if(row < M){
                float* dst = C + (size_t)row*N + bn + c0;
                #pragma unroll
                for(int c = 0; c < 32; c++){
                    float v = __uint_as_float(d[c]) + (bias ? bias[bn+c0+c] : 0.f);
                    if(RELU) v = fmaxf(v, 0.f);
                    dst[c] = v;
                }
            }
        }
        TCGEN05_FENCE_BEFORE();
    }
    __syncthreads();
    CLUSTER_SYNC();
    if(wid == 0){ TCGEN05_DEALLOC(tmem, 128); }
#else
    (void)A; (void)Bw; (void)bias; (void)C; (void)M; (void)N; (void)K3;
#endif
}

/* a_s/a_d dots for layer 2. one warp per (n,h) */
__global__ void k_attdot(const float* __restrict__ xp, const float* __restrict__ as_,
                         const float* __restrict__ ad_, float* __restrict__ asn,
                         float* __restrict__ adn, int Nn){
    int w = (blockIdx.x*blockDim.x + threadIdx.x) >> 5;
    int lane = threadIdx.x & 31;
    if(w >= Nn*3) return;
    int n = w/3, h = w - n*3;
    const float* row = xp + (size_t)n*F3 + h*EMB;
    float s = 0.f, d = 0.f;
    for(int c = lane; c < EMB; c += 32){ float v = row[c]; s += v*as_[h*EMB+c]; d += v*ad_[h*EMB+c]; }
    for(int o = 16; o; o >>= 1){ s += __shfl_down_sync(~0u,s,o); d += __shfl_down_sync(~0u,d,o); }
    if(!lane){ asn[n*3+h] = s; adn[n*3+h] = d; }
}

/* edge pass 1: padded-CSR scatter + segment max */
__global__ void k_edge_pass1(const int* __restrict__ sA, const int* __restrict__ tA,
                             int* __restrict__ cnt, int* __restrict__ eid,
                             unsigned* __restrict__ emax,
                             const float* __restrict__ asn, const float* __restrict__ adn,
                             int nSelf){
    int i = blockIdx.x*blockDim.x + threadIdx.x;
    if(i >= NEDGE + nSelf) return;
    int s, t;
    if(i < NEDGE){ s = sA[i]; t = tA[i]; if((s|t) < 0) return; }
    else { s = t = i - NEDGE; }
    int pos = atomicAdd(&cnt[t], 1);
    eid[t*DCAP + pos] = i;
    #pragma unroll
    for(int h = 0; h < 3; h++){
        float e = asn[s*3+h] + adn[t*3+h];
        e = e > 0.f ? e : 0.2f*e;
        atomicMax(&emax[t*3+h], f2o(e));
    }
}

/* aggregation (384 thr): padded CSR; staging computes softmax numerators
   in-block (den folded into final scale), float4 gather, packed split stores */
__global__ __launch_bounds__(384)
void k_agg(const int* __restrict__ cnt, const int* __restrict__ eid,
           const int* __restrict__ sA, const float* __restrict__ xp,
           const float* __restrict__ asn, const float* __restrict__ adn,
           const unsigned* __restrict__ emax,
           const float* __restrict__ bias, __nv_bfloat16* __restrict__ out){
    int n = blockIdx.x, t = threadIdx.x;
    int h = t >> 7, q = t & 127;
    __shared__ int   ss[DCAP];
    __shared__ float sw[3][DCAP];
    int deg = cnt[n];
    const int* eb = eid + n*DCAP;
    float adc[3], emc[3];
    #pragma unroll
    for(int hh = 0; hh < 3; hh++){ adc[hh] = adn[n*3+hh]; emc[hh] = o2f(emax[n*3+hh]); }
    for(int e = t; e < deg; e += 384){
        int i = eb[e];
        int s = (i < NEDGE) ? sA[i] : (i - NEDGE);
        ss[e] = s;
        #pragma unroll
        for(int hh = 0; hh < 3; hh++){
            float ev = asn[s*3+hh] + adc[hh];
            ev = ev > 0.f ? ev : 0.2f*ev;
            sw[hh][e] = expf(ev - emc[hh]);
        }
    }
    __syncthreads();
    float4 acc = make_float4(0,0,0,0);
    float sumw = 0.f;
    #pragma unroll 2
    for(int e = 0; e < deg; e++){
        float w = sw[h][e];
        sumw += w;
        float4 xv = ((const float4*)(xp + (size_t)ss[e]*F3))[h*128 + q];
        acc.x += w*xv.x; acc.y += w*xv.y; acc.z += w*xv.z; acc.w += w*xv.w;
    }
    float rd = 1.f/fmaxf(sumw, 1e-16f);
    int j0 = h*512 + q*4;
    float4 bv = ((const float4*)bias)[h*128 + q];
    float v0 = acc.x*rd + bv.x, v1 = acc.y*rd + bv.y;
    float v2 = acc.z*rd + bv.z, v3 = acc.w*rd + bv.w;
    __nv_bfloat16 h0,l0,h1,l1,h2,l2,h3,l3;
    split2(v0,h0,l0); split2(v1,h1,l1); split2(v2,h2,l2); split2(v3,h3,l3);
    uint64_t hiP = (uint64_t)bfbits(h0) | ((uint64_t)bfbits(h1)<<16)
                 | ((uint64_t)bfbits(h2)<<32) | ((uint64_t)bfbits(h3)<<48);
    uint64_t loP = (uint64_t)bfbits(l0) | ((uint64_t)bfbits(l1)<<16)
                 | ((uint64_t)bfbits(l2)<<32) | ((uint64_t)bfbits(l3)<<48);
    char* Ob = (char*)out;
    *(uint64_t*)(Ob + swaddr(n, j0,        3*F3)) = hiP;
    *(uint64_t*)(Ob + swaddr(n, F3 + j0,   3*F3)) = loP;
    *(uint64_t*)(Ob + swaddr(n, 2*F3 + j0, 3*F3)) = hiP;
}

__global__ void k_bnstats(const float* __restrict__ h, float* __restrict__ bsum,
                          float* __restrict__ bsq, int M){
    int t = threadIdx.x;
    int r0 = blockIdx.x*64;
    float s0=0,q0=0,s1=0,q1=0;
    int rend = min(r0+64, M);
    for(int r = r0; r < rend; r++){
        float v0 = h[(size_t)r*EMB + t], v1 = h[(size_t)r*EMB + t + 256];
        s0 += v0; q0 += v0*v0; s1 += v1; q1 += v1*v1;
    }
    atomicAdd(&bsum[t], s0);     atomicAdd(&bsq[t], q0);
    atomicAdd(&bsum[t+256], s1); atomicAdd(&bsq[t+256], q1);
}

__global__ void k_rnorm2(const float* __restrict__ p1, const float* __restrict__ p2){
    __shared__ float red[512];
    const float* p = blockIdx.x ? p2 : p1;
    int t = threadIdx.x;
    float v = p[t]; red[t] = v*v; __syncthreads();
    for(int o = 256; o; o >>= 1){ if(t < o) red[t] += red[t+o]; __syncthreads(); }
    if(!t) d_rnorm[blockIdx.x] = rsqrtf(red[0]);
}

__global__ void k_bnapply(const float* __restrict__ h, const float* __restrict__ g,
                          const float* __restrict__ be, const float* __restrict__ p,
                          const float* __restrict__ bsum, const float* __restrict__ bsq,
                          float* __restrict__ y, float* __restrict__ score, int M, int rsel){
    int row = blockIdx.x, t = threadIdx.x;
    float invM = 1.f/(float)M;
    float dot = 0.f;
    #pragma unroll
    for(int u = 0; u < 2; u++){
        int c = t + u*256;
        float m = bsum[c]*invM;
        float v = bsq[c]*invM - m*m;
        float yy = (h[(size_t)row*EMB + c] - m)*rsqrtf(v + 1e-5f)*g[c] + be[c];
        y[(size_t)row*EMB + c] = yy;
        dot += yy*p[c];
    }
    __shared__ float red[256];
    red[t] = dot; __syncthreads();
    for(int o = 128; o; o >>= 1){ if(t < o) red[t] += red[t+o]; __syncthreads(); }
    if(!t) score[row] = tanhf(red[0]*d_rnorm[rsel]);
}

/* top-k sort: writes perm indices, sorted scores, and (optional) mapping */
__global__ void k_topk_sort(const float* __restrict__ score, int* map,
                            int* __restrict__ prm, float* __restrict__ psc,
                            int n_per, int keep){
    int b = blockIdx.x, t = threadIdx.x;      /* 512 */
    __shared__ float sk[512]; __shared__ int si[512];
    sk[t] = (t < n_per) ? score[b*n_per + t] : -3.0e38f;
    si[t] = t;
    __syncthreads();
    for(int k = 2; k <= 512; k <<= 1)
        for(int j = k>>1; j > 0; j >>= 1){
            int x = t ^ j;
            if(x > t){
                bool up = ((t & k) == 0);
                float a = sk[t], c = sk[x];
                bool sw = up ? (a < c) : (a > c);
                if(sw){ sk[t]=c; sk[x]=a; int ti=si[t]; si[t]=si[x]; si[x]=ti; }
            }
            __syncthreads();
        }
    if(map){
        if(t < n_per) map[b*n_per + t] = -1;
        __syncthreads();
        if(t < keep) map[b*n_per + si[t]] = b*keep + t;
    }
    prm[b*512 + t] = si[t];
    psc[b*512 + t] = sk[t];
}

/* gather: grid (NB, nch). 8 rows/CTA: scale, split store, pool partials */
__global__ void k_gather(const float* __restrict__ y, const int* __restrict__ prm,
                         const float* __restrict__ psc, __nv_bfloat16* split,
                         float* __restrict__ pm, float* __restrict__ ps,
                         int n_per, int keep, int nch){
    int b = blockIdx.x, c = blockIdx.y, t = threadIdx.x;   /* 512 */
    char* Sb = (char*)split;
    float mx = -3.0e38f, sm = 0.f;
    #pragma unroll
    for(int rr = 0; rr < 8; rr++){
        int r = c*8 + rr;
        if(r < keep){
            int node = b*n_per + prm[b*512 + r];
            float s = psc[b*512 + r];
            float v = y[(size_t)node*EMB + t]*s;
            mx = fmaxf(mx, v); sm += v;
            if(split){
                int row = b*keep + r;
                __nv_bfloat16 hi, lo; split2(v, hi, lo);
                *(__nv_bfloat16*)(Sb + swaddr(row, t,         3*EMB)) = hi;
                *(__nv_bfloat16*)(Sb + swaddr(row, EMB + t,   3*EMB)) = lo;
                *(__nv_bfloat16*)(Sb + swaddr(row, 2*EMB + t, 3*EMB)) = hi;
            }
        }
    }
    pm[((size_t)b*nch + c)*512 + t] = mx;
    ps[((size_t)b*nch + c)*512 + t] = sm;
}

__global__ void k_relabel(const int* __restrict__ ei){
    int i = blockIdx.x*blockDim.x + threadIdx.x;
    if(i >= NEDGE) return;
    d_s2[i] = d_map1[ei[i]];
    d_t2[i] = d_map1[ei[NEDGE + i]];
}

/* fused head: pool finalize (both layers) + MLP1 + MLP2. one block per graph */
__global__ __launch_bounds__(512)
void k_head(const float* __restrict__ Wl1, const float* __restrict__ bl1,
            const float* __restrict__ Wl2, const float* __restrict__ bl2,
            float* __restrict__ out){
    int b = blockIdx.x, t = threadIdx.x;      /* 512 */
    __shared__ float xg[1024];
    __shared__ float tt[512];
    float mx1 = -3.0e38f, sm1 = 0.f;
    for(int c = 0; c < NCH1; c++){
        mx1 = fmaxf(mx1, d_pm1[((size_t)b*NCH1 + c)*512 + t]);
        sm1 += d_ps1[((size_t)b*NCH1 + c)*512 + t];
    }
    float mx2 = -3.0e38f, sm2 = 0.f;
    for(int c = 0; c < NCH2; c++){
        mx2 = fmaxf(mx2, d_pm2[((size_t)b*NCH2 + c)*512 + t]);
        sm2 += d_ps2[((size_t)b*NCH2 + c)*512 + t];
    }
    xg[t]       = mx1 + mx2;
    xg[512 + t] = sm1/(float)KP1 + sm2/(float)KP2;
    __syncthreads();
    float s = bl1[t];
    for(int k = 0; k < 1024; k++) s += xg[k]*Wl1[k*512 + t];
    tt[t] = fmaxf(s, 0.f);
    __syncthreads();
    if(t < 256){
        float o = bl2[t];
        for(int k = 0; k < 512; k++) o += tt[k]*Wl2[k*256 + t];
        out[b*256 + t] = o;
    }
}

/* -------------------------------- host ------------------------------------ */
#define GETP(T, v, sym_) T* v; { void* _p; cudaGetSymbolAddress(&_p, sym_); v = (T*)_p; }

extern "C" void kernel_launch(void* const* d_in, const int* in_sizes, int n_in,
                              void* d_out, int out_size){
    (void)in_sizes; (void)n_in; (void)out_size;
    const float* x   = (const float*)d_in[0];
    const int*   ei  = (const int*)  d_in[1];
    const float* W1  = (const float*)d_in[2];
    const float* as1 = (const float*)d_in[3];
    const float* ad1 = (const float*)d_in[4];
    const float* bc1 = (const float*)d_in[5];
    const float* Wh1 = (const float*)d_in[6];
    const float* bh1 = (const float*)d_in[7];
    const float* g1  = (const float*)d_in[8];
    const float* be1 = (const float*)d_in[9];
    const float* p1  = (const float*)d_in[10];
    const float* W2  = (const float*)d_in[11];
    const float* as2 = (const float*)d_in[12];
    const float* ad2 = (const float*)d_in[13];
    const float* bc2 = (const float*)d_in[14];
    const float* Wh2 = (const float*)d_in[15];
    const float* bh2 = (const float*)d_in[16];
    const float* g2  = (const float*)d_in[17];
    const float* be2 = (const float*)d_in[18];
    const float* p2  = (const float*)d_in[19];
    const float* Wl1 = (const float*)d_in[20];
    const float* bl1 = (const float*)d_in[21];
    const float* Wl2 = (const float*)d_in[22];
    const float* bl2 = (const float*)d_in[23];

    GETP(float, xp1, d_xp1)   GETP(float, asn1, d_asn1) GETP(float, adn1, d_adn1)
    GETP(unsigned, emax1, d_emax1)
    GETP(int, cnt1, d_cnt1)   GETP(int, eid1, d_eid1)   GETP(float, h1, d_h1)
    GETP(float, y1, d_y1)     GETP(float, sc1, d_sc1)   GETP(int, map1, d_map1)
    GETP(int, s2, d_s2)       GETP(int, t2, d_t2)
    GETP(float, xp2, d_xp2)   GETP(float, asn2, d_asn2) GETP(float, adn2, d_adn2)
    GETP(unsigned, emax2, d_emax2)
    GETP(int, cnt2, d_cnt2)   GETP(int, eid2, d_eid2)   GETP(float, h2, d_h2)
    GETP(float, y2, d_y2)     GETP(float, sc2, d_sc2)
    GETP(float, bsum1, d_bsum1) GETP(float, bsq1, d_bsq1)
    GETP(float, bsum2, d_bsum2) GETP(float, bsq2, d_bsq2)
    GETP(int, prm, d_prm)     GETP(float, psc, d_psc)
    GETP(float, pm1, d_pm1)   GETP(float, ps1, d_ps1)
    GETP(float, pm2, d_pm2)   GETP(float, ps2, d_ps2)
    GETP(__nv_bfloat16, a16, d_a16)
    GETP(__nv_bfloat16, bw1, d_bw1) GETP(__nv_bfloat16, bw2, d_bw2) GETP(__nv_bfloat16, bw3, d_bw3)

    cudaFuncSetAttribute(k_tgemm<0>, cudaFuncAttributeMaxDynamicSharedMemorySize, TG_SMEM);
    cudaFuncSetAttribute(k_tgemm<1>, cudaFuncAttributeMaxDynamicSharedMemorySize, TG_SMEM);

    dim3 tb(32,8);

    /* idx 0 */ k_zero_all<<<CDIV(NN1*3,256),256>>>();
    /* idx 1 */ k_xw1att<<<NN1,256>>>(x, W1, as1, ad1);
    /* idx 2 */ k_edge_pass1<<<CDIV(E1TOT,256),256>>>(ei, ei+NEDGE, cnt1, eid1, emax1, asn1, adn1, NN1);
    /* idx 3: ncu capture -> k_agg */
    k_agg<<<NN1,384>>>(cnt1, eid1, ei, xp1, asn1, adn1, emax1, bc1, a16);

    k_split_bT<<<dim3(F3/32,512/32),tb>>>(Wh1, bw1, F3, 512);
    k_tgemm<1><<<dim3(4, NN1/128),TG_THREADS,TG_SMEM>>>(a16, bw1, bh1, h1, NN1, 512, 3*F3);

    k_split_bT<<<dim3(EMB/32,F3/32),tb>>>(W2, bw2, EMB, F3);
    k_split_bT<<<dim3(F3/32,512/32),tb>>>(Wh2, bw3, F3, 512);
    k_rnorm2<<<2,512>>>(p1, p2);

    k_bnstats<<<CDIV(NN1,64),256>>>(h1, bsum1, bsq1, NN1);
    k_bnapply<<<NN1,256>>>(h1, g1, be1, p1, bsum1, bsq1, y1, sc1, NN1, 0);
    k_topk_sort<<<NBATCH,512>>>(sc1, map1, prm, psc, 512, KP1);
    k_gather<<<dim3(NBATCH,NCH1),512>>>(y1, prm, psc, a16, pm1, ps1, 512, KP1, NCH1);
    k_relabel<<<CDIV(NEDGE,256),256>>>(ei);

    /* ---- layer 2 ---- */
    k_tgemm<0><<<dim3(F3/128, CDIV(NN2,128)),TG_THREADS,TG_SMEM>>>(a16, bw2, (const float*)nullptr, xp2, NN2, F3, 3*EMB);

    k_attdot<<<CDIV(NN2*3*32,256),256>>>(xp2, as2, ad2, asn2, adn2, NN2);
    k_edge_pass1<<<CDIV(E2TOT,256),256>>>(s2, t2, cnt2, eid2, emax2, asn2, adn2, NN2);
    k_agg<<<NN2,384>>>(cnt2, eid2, s2, xp2, asn2, adn2, emax2, bc2, a16);

    k_tgemm<1><<<dim3(4, CDIV(NN2,128)),TG_THREADS,TG_SMEM>>>(a16, bw3, bh2, h2, NN2, 512, 3*F3);

    k_bnstats<<<CDIV(NN2,64),256>>>(h2, bsum2, bsq2, NN2);
    k_bnapply<<<NN2,256>>>(h2, g2, be2, p2, bsum2, bsq2, y2, sc2, NN2, 1);
    k_topk_sort<<<NBATCH,512>>>(sc2, (int*)nullptr, prm, psc, KP1, KP2);
    k_gather<<<dim3(NBATCH,NCH2),512>>>(y2, prm, psc, (__nv_bfloat16*)nullptr, pm2, ps2, KP1, KP2, NCH2);

    /* ---- fused head ---- */
    k_head<<<NBATCH,512>>>(Wl1, bl1, Wl2, bl2, (float*)d_out);
}

// round 13
// speedup vs baseline: 1.0592x; 1.0592x over previous
#include <cuda_runtime.h>
#include <cuda_bf16.h>
#include <math.h>
#include <stdint.h>

#define NBATCH 16
#define NEDGE  131072
#define NN1    8192
#define KP1    410
#define KP2    205
#define NN2    6560      /* 16*410 */
#define EMB    512
#define F3     1536
#define E1TOT  (NEDGE+NN1)
#define E2TOT  (NEDGE+NN2)
#define NCH1   52        /* CDIV(KP1,8) */
#define NCH2   26        /* CDIV(KP2,8) */
#define DCAP   128       /* padded-CSR per-node capacity (max in-degree ~45) */
#define CDIV(a,b) (((a)+(b)-1)/(b))

/* tcgen05 availability: only in arch-specific device passes. */
#if !defined(__CUDA_ARCH__) || defined(__CUDA_ARCH_FEAT_SM103_ALL) || \
    defined(__CUDA_ARCH_FEAT_SM100_ALL) || defined(__CUDA_ARCH_SPECIFIC__) || \
    defined(__CUDA_ARCH_FAMILY_SPECIFIC__)
#define TG_TC 1
#else
#define TG_TC 0
#endif

/* ================= PTX helpers ================= */
__device__ __forceinline__ uint32_t smem_u32(const void* p){
    uint32_t a;
    asm("{ .reg .u64 t; cvta.to.shared.u64 t, %1; cvt.u32.u64 %0, t; }" : "=r"(a) : "l"(p));
    return a;
}
#define TCGEN05_ALLOC(sa, n) \
    asm volatile("tcgen05.alloc.cta_group::1.sync.aligned.shared::cta.b32 [%0], %1;" \
        :: "r"((uint32_t)(sa)), "r"((uint32_t)(n)) : "memory")
#define TCGEN05_DEALLOC(tm, n) \
    asm volatile("tcgen05.dealloc.cta_group::1.sync.aligned.b32 %0, %1;" :: "r"(tm), "r"((uint32_t)(n)))
#define TCGEN05_RELINQ() \
    asm volatile("tcgen05.relinquish_alloc_permit.cta_group::1.sync.aligned;")
#define TCGEN05_COMMIT(mb) \
    asm volatile("tcgen05.commit.cta_group::1.mbarrier::arrive::one.shared::cluster.b64 [%0];" \
        :: "r"((uint32_t)(mb)) : "memory")
#define TCGEN05_FENCE_AFTER()  asm volatile("tcgen05.fence::after_thread_sync;" ::: "memory")
#define TCGEN05_FENCE_BEFORE() asm volatile("tcgen05.fence::before_thread_sync;" ::: "memory")
#define TCGEN05_WAIT_LD()      asm volatile("tcgen05.wait::ld.sync.aligned;" ::: "memory")
#define MBARRIER_INIT(mb, c) \
    asm volatile("mbarrier.init.shared.b64 [%0], %1;" :: "r"((uint32_t)(mb)), "r"((uint32_t)(c)) : "memory")
#define MBARRIER_EXPECT_TX(mb, n) \
    asm volatile("mbarrier.arrive.expect_tx.shared.b64 _, [%0], %1;" \
        :: "r"((uint32_t)(mb)), "r"((uint32_t)(n)) : "memory")
#define MBARRIER_WAIT_PARITY(mb, ph) do { \
    uint32_t _m = (uint32_t)(mb), _p = (uint32_t)(ph), _d; \
    asm volatile("{\n\t.reg .pred p;\n\t" \
        "mbarrier.try_wait.parity.acquire.cta.shared::cta.b64 p, [%1], %2;\n\t" \
        "selp.b32 %0, 1, 0, p;\n\t}" : "=r"(_d) : "r"(_m), "r"(_p) : "memory"); \
    if(!_d){ \
        asm volatile("{\n\t.reg .pred P1;\n\t" \
            "WL_%=:\n\t" \
            "mbarrier.try_wait.parity.acquire.cta.shared::cta.b64 P1, [%0], %1, 0x989680;\n\t" \
            "@P1 bra.uni WD_%=;\n\t" \
            "bra.uni WL_%=;\n\t" \
            "WD_%=:\n\t}" :: "r"(_m), "r"(_p) : "memory"); \
    } } while(0)
#define BULK_G2S(dst, src, sz, mb) \
    asm volatile("cp.async.bulk.shared::cta.global.mbarrier::complete_tx::bytes [%0], [%1], %2, [%3];" \
        :: "r"((uint32_t)(dst)), "l"(src), "r"((uint32_t)(sz)), "r"((uint32_t)(mb)) : "memory")
#define TCGEN05_LD_X32(r, ta) \
    asm volatile("tcgen05.ld.sync.aligned.32x32b.x32.b32 " \
        "{%0, %1, %2, %3, %4, %5, %6, %7, %8, %9, %10, %11, %12, %13, %14, %15, " \
        " %16, %17, %18, %19, %20, %21, %22, %23, %24, %25, %26, %27, %28, %29, %30, %31}, [%32];" \
        : "=r"((r)[0]),  "=r"((r)[1]),  "=r"((r)[2]),  "=r"((r)[3]), \
          "=r"((r)[4]),  "=r"((r)[5]),  "=r"((r)[6]),  "=r"((r)[7]), \
          "=r"((r)[8]),  "=r"((r)[9]),  "=r"((r)[10]), "=r"((r)[11]), \
          "=r"((r)[12]), "=r"((r)[13]), "=r"((r)[14]), "=r"((r)[15]), \
          "=r"((r)[16]), "=r"((r)[17]), "=r"((r)[18]), "=r"((r)[19]), \
          "=r"((r)[20]), "=r"((r)[21]), "=r"((r)[22]), "=r"((r)[23]), \
          "=r"((r)[24]), "=r"((r)[25]), "=r"((r)[26]), "=r"((r)[27]), \
          "=r"((r)[28]), "=r"((r)[29]), "=r"((r)[30]), "=r"((r)[31]) \
        : "r"(ta))
#if TG_TC
__device__ __forceinline__ void mma_f16_ss(uint32_t d, uint64_t a, uint64_t b,
                                           uint32_t idesc, uint32_t acc){
    uint32_t z = 0;
    asm volatile("{\n\t.reg .pred p;\n\tsetp.ne.u32 p, %5, 0;\n\t"
        "tcgen05.mma.cta_group::1.kind::f16 [%0], %1, %2, %3, {%4, %4, %4, %4}, p;\n\t}"
        :: "r"(d), "l"(a), "l"(b), "r"(idesc), "r"(z), "r"(acc) : "memory");
}
#endif
static __device__ __forceinline__ uint64_t mk_desc(uint32_t base){
    const uint64_t B = (uint64_t(2) << 61) | (uint64_t(1) << 46)
                     | (uint64_t(64) << 32) | (uint64_t(1) << 16);
    return B | ((uint64_t)(base >> 4) & 0x3FFF);
}

/* byte offset of bf16 element (row, k3) in tile-chunk-major pre-swizzled layout */
__device__ __forceinline__ size_t swaddr(int row, int k3, int K3){
    int nchunk = K3 >> 6;
    int mb = row >> 7, r = row & 127;
    int kb = k3 << 1;
    int c = kb >> 7, q = kb & 127;
    int blk = (q >> 4) ^ (r & 7);
    return ((((size_t)mb*nchunk + c)*128 + r) << 7) + (blk << 4) + (q & 15);
}
__device__ __forceinline__ uint16_t bfbits(__nv_bfloat16 h){
    return *reinterpret_cast<uint16_t*>(&h);
}

/* ---------------- scratch ---------------- */
__device__ __align__(16) float d_xp1 [NN1*F3];
__device__ float    d_asn1[NN1*3], d_adn1[NN1*3];
__device__ unsigned d_emax1[NN1*3];
__device__ int      d_cnt1[NN1], d_eid1[NN1*DCAP];
__device__ float    d_h1  [NN1*EMB];
__device__ float    d_y1  [NN1*EMB];
__device__ float    d_sc1 [NN1];
__device__ int      d_map1[NN1];
__device__ int      d_s2  [NEDGE], d_t2[NEDGE];

__device__ __align__(16) float d_xp2 [NN2*F3];
__device__ float    d_asn2[NN2*3], d_adn2[NN2*3];
__device__ unsigned d_emax2[NN2*3];
__device__ int      d_cnt2[NN2], d_eid2[NN2*DCAP];
__device__ float    d_h2  [NN2*EMB];
__device__ float    d_y2  [NN2*EMB];
__device__ float    d_sc2 [NN2];

__device__ float    d_bsum1[EMB], d_bsq1[EMB], d_bsum2[EMB], d_bsq2[EMB];
__device__ float    d_rnorm[2];

/* top-k staging + pool partials */
__device__ int      d_prm [NBATCH*512];
__device__ float    d_psc [NBATCH*512];
__device__ float    d_pm1 [NBATCH*NCH1*512], d_ps1[NBATCH*NCH1*512];
__device__ float    d_pm2 [NBATCH*NCH2*512], d_ps2[NBATCH*NCH2*512];

/* bf16 split buffers (tile-chunk-major pre-swizzled) */
__device__ __align__(128) __nv_bfloat16 d_a16 [(size_t)NN1*3*F3];
__device__ __align__(128) __nv_bfloat16 d_bw1 [512*3*F3];
__device__ __align__(128) __nv_bfloat16 d_bw2 [F3*3*EMB];
__device__ __align__(128) __nv_bfloat16 d_bw3 [512*3*F3];

/* ------------------------------- helpers ---------------------------------- */
__device__ __forceinline__ unsigned f2o(float f){
    unsigned u = __float_as_uint(f);
    return (u & 0x80000000u) ? ~u : (u | 0x80000000u);
}
__device__ __forceinline__ float o2f(unsigned e){
    return (e & 0x80000000u) ? __uint_as_float(e & 0x7FFFFFFFu)
                             : __uint_as_float(~e);
}
__device__ __forceinline__ void split2(float v, __nv_bfloat16& hi, __nv_bfloat16& lo){
    hi = __float2bfloat16(v);
    lo = __float2bfloat16(v - __bfloat162float(hi));
}

__global__ void k_zero_all(){
    int i = blockIdx.x*blockDim.x + threadIdx.x;
    if(i < NN1*3){ d_emax1[i] = 0u; }
    if(i < NN1){ d_cnt1[i] = 0; }
    if(i < NN2*3){ d_emax2[i] = 0u; }
    if(i < NN2){ d_cnt2[i] = 0; }
    if(i < EMB){ d_bsum1[i]=0.f; d_bsq1[i]=0.f; d_bsum2[i]=0.f; d_bsq2[i]=0.f; }
}

/* W[K,N] -> B'[n][3K]=[hi|hi|lo] in tile-chunk-major pre-swizzled layout */
__global__ void k_split_bT(const float* __restrict__ W, __nv_bfloat16* __restrict__ O,
                           int K, int N){
    __shared__ float tile[32][33];
    int k0 = blockIdx.x*32, n0 = blockIdx.y*32;
    int tx = threadIdx.x, ty = threadIdx.y;
    int K3 = 3*K;
    char* Ob = (char*)O;
    #pragma unroll
    for(int i = ty; i < 32; i += 8)
        tile[i][tx] = W[(size_t)(k0+i)*N + n0 + tx];
    __syncthreads();
    #pragma unroll
    for(int i = ty; i < 32; i += 8){
        int n = n0 + i, k = k0 + tx;
        float w = tile[tx][i];
        __nv_bfloat16 hi, lo; split2(w, hi, lo);
        *(__nv_bfloat16*)(Ob + swaddr(n, k,       K3)) = hi;
        *(__nv_bfloat16*)(Ob + swaddr(n, K + k,   K3)) = hi;
        *(__nv_bfloat16*)(Ob + swaddr(n, 2*K + k, K3)) = lo;
    }
}

/* fused: xp1 = x@W1 and attention dots. one block (256 thr) per node */
__global__ void k_xw1att(const float* __restrict__ x, const float* __restrict__ W,
                         const float* __restrict__ as_, const float* __restrict__ ad_){
    int n = blockIdx.x, t = threadIdx.x;
    float x0 = x[n*3], x1 = x[n*3+1], x2 = x[n*3+2];
    float sa[3] = {0,0,0}, da[3] = {0,0,0};
    #pragma unroll
    for(int u = 0; u < 6; u++){
        int j = t + u*256;
        float v = x0*W[j] + x1*W[F3+j] + x2*W[2*F3+j];
        d_xp1[(size_t)n*F3 + j] = v;
        sa[u>>1] += v*as_[j]; da[u>>1] += v*ad_[j];
    }
    __shared__ float R[6*256];
    #pragma unroll
    for(int h = 0; h < 3; h++){ R[h*256+t] = sa[h]; R[(3+h)*256+t] = da[h]; }
    __syncthreads();
    for(int off = 128; off; off >>= 1){
        if(t < off){
            #pragma unroll
            for(int ch = 0; ch < 6; ch++) R[ch*256+t] += R[ch*256+t+off];
        }
        __syncthreads();
    }
    if(t < 3) d_asn1[n*3+t] = R[t*256];
    else if(t < 6) d_adn1[n*3 + (t-3)] = R[t*256];
}

/* warp-specialized tcgen05 bf16 SS GEMM with bulk loads (non-cluster, R11) */
#define TG_STAGES 3
#define TG_THREADS 192
#define TG_SMEM (1024 + TG_STAGES*32768)
template<int RELU>
__global__ __launch_bounds__(TG_THREADS)
void k_tgemm(const __nv_bfloat16* __restrict__ A, const __nv_bfloat16* __restrict__ Bw,
             const float* __restrict__ bias, float* __restrict__ C,
             int M, int N, int K3){
#if TG_TC
    extern __shared__ char smem[];
    uint32_t sb = smem_u32(smem);
    int tid = threadIdx.x, wid = tid >> 5, lane = tid & 31;
    int bm = blockIdx.y*128, bn = blockIdx.x*128;
    int nchunk = K3 >> 6;

    if(wid == 0){ TCGEN05_ALLOC(sb, 128); TCGEN05_RELINQ(); }
    if(tid == 0){
        #pragma unroll
        for(int s = 0; s < TG_STAGES; s++){
            MBARRIER_INIT(sb + 8 + 8*s, 1);
            MBARRIER_INIT(sb + 40 + 8*s, 1);
        }
    }
    __syncthreads();
    uint32_t tmem;
    asm volatile("ld.shared.b32 %0, [%1];" : "=r"(tmem) : "r"(sb));

    if(wid == 4 && lane == 0){
        const char* abase = (const char*)A + ((size_t)(bm >> 7)*nchunk << 14);
        const char* bbase = (const char*)Bw + ((size_t)(bn >> 7)*nchunk << 14);
        for(int kc = 0; kc < nchunk; kc++){
            int b = kc % TG_STAGES, r = kc / TG_STAGES;
            if(r > 0) MBARRIER_WAIT_PARITY(sb + 40 + 8*b, (r-1) & 1);
            uint32_t st = sb + 1024 + b*32768;
            MBARRIER_EXPECT_TX(sb + 8 + 8*b, 32768);
            BULK_G2S(st,         abase + ((size_t)kc << 14), 16384, sb + 8 + 8*b);
            BULK_G2S(st + 16384, bbase + ((size_t)kc << 14), 16384, sb + 8 + 8*b);
        }
    }
    if(wid == 5 && lane == 0){
        const uint32_t idesc = (1u<<4)|(1u<<7)|(1u<<10)|(16u<<17)|(8u<<24);
        for(int kc = 0; kc < nchunk; kc++){
            int b = kc % TG_STAGES, r = kc / TG_STAGES;
            MBARRIER_WAIT_PARITY(sb + 8 + 8*b, r & 1);
            uint64_t ad = mk_desc(sb + 1024 + b*32768);
            uint64_t bd = mk_desc(sb + 1024 + b*32768 + 16384);
            #pragma unroll
            for(int k = 0; k < 4; k++)
                mma_f16_ss(tmem, ad + k*2, bd + k*2, idesc, (kc > 0) | (k > 0));
            TCGEN05_COMMIT(sb + 40 + 8*b);
        }
        int kl = nchunk - 1;
        MBARRIER_WAIT_PARITY(sb + 40 + 8*(kl % TG_STAGES), (kl / TG_STAGES) & 1);
    }
    __syncthreads();
    TCGEN05_FENCE_AFTER();

    if(wid < 4){
        int row = bm + wid*32 + lane;
        #pragma unroll
        for(int c0 = 0; c0 < 128; c0 += 32){
            uint32_t d[32];
            TCGEN05_LD_X32(d, tmem + c0);
            TCGEN05_WAIT_LD();
            if(row < M){
                float* dst = C + (size_t)row*N + bn + c0;
                #pragma unroll
                for(int c = 0; c < 32; c++){
                    float v = __uint_as_float(d[c]) + (bias ? bias[bn+c0+c] : 0.f);
                    if(RELU) v = fmaxf(v, 0.f);
                    dst[c] = v;
                }
            }
        }
        TCGEN05_FENCE_BEFORE();
    }
    __syncthreads();
    if(wid == 0){ TCGEN05_DEALLOC(tmem, 128); }
#else
    (void)A; (void)Bw; (void)bias; (void)C; (void)M; (void)N; (void)K3;
#endif
}

/* a_s/a_d dots for layer 2. one warp per (n,h) */
__global__ void k_attdot(const float* __restrict__ xp, const float* __restrict__ as_,
                         const float* __restrict__ ad_, float* __restrict__ asn,
                         float* __restrict__ adn, int Nn){
    int w = (blockIdx.x*blockDim.x + threadIdx.x) >> 5;
    int lane = threadIdx.x & 31;
    if(w >= Nn*3) return;
    int n = w/3, h = w - n*3;
    const float* row = xp + (size_t)n*F3 + h*EMB;
    float s = 0.f, d = 0.f;
    for(int c = lane; c < EMB; c += 32){ float v = row[c]; s += v*as_[h*EMB+c]; d += v*ad_[h*EMB+c]; }
    for(int o = 16; o; o >>= 1){ s += __shfl_down_sync(~0u,s,o); d += __shfl_down_sync(~0u,d,o); }
    if(!lane){ asn[n*3+h] = s; adn[n*3+h] = d; }
}

/* edge pass 1: padded-CSR scatter + segment max */
__global__ void k_edge_pass1(const int* __restrict__ sA, const int* __restrict__ tA,
                             int* __restrict__ cnt, int* __restrict__ eid,
                             unsigned* __restrict__ emax,
                             const float* __restrict__ asn, const float* __restrict__ adn,
                             int nSelf){
    int i = blockIdx.x*blockDim.x + threadIdx.x;
    if(i >= NEDGE + nSelf) return;
    int s, t;
    if(i < NEDGE){ s = sA[i]; t = tA[i]; if((s|t) < 0) return; }
    else { s = t = i - NEDGE; }
    int pos = atomicAdd(&cnt[t], 1);
    eid[t*DCAP + pos] = i;
    #pragma unroll
    for(int h = 0; h < 3; h++){
        float e = asn[s*3+h] + adn[t*3+h];
        e = e > 0.f ? e : 0.2f*e;
        atomicMax(&emax[t*3+h], f2o(e));
    }
}

/* aggregation (384 thr): padded CSR; staging computes softmax numerators
   in-block (den folded into final scale), float4 gather, packed split stores */
__global__ __launch_bounds__(384)
void k_agg(const int* __restrict__ cnt, const int* __restrict__ eid,
           const int* __restrict__ sA, const float* __restrict__ xp,
           const float* __restrict__ asn, const float* __restrict__ adn,
           const unsigned* __restrict__ emax,
           const float* __restrict__ bias, __nv_bfloat16* __restrict__ out){
    int n = blockIdx.x, t = threadIdx.x;
    int h = t >> 7, q = t & 127;
    __shared__ int   ss[DCAP];
    __shared__ float sw[3][DCAP];
    int deg = cnt[n];
    const int* eb = eid + n*DCAP;
    float adc[3], emc[3];
    #pragma unroll
    for(int hh = 0; hh < 3; hh++){ adc[hh] = adn[n*3+hh]; emc[hh] = o2f(emax[n*3+hh]); }
    for(int e = t; e < deg; e += 384){
        int i = eb[e];
        int s = (i < NEDGE) ? sA[i] : (i - NEDGE);
        ss[e] = s;
        #pragma unroll
        for(int hh = 0; hh < 3; hh++){
            float ev = asn[s*3+hh] + adc[hh];
            ev = ev > 0.f ? ev : 0.2f*ev;
            sw[hh][e] = expf(ev - emc[hh]);
        }
    }
    __syncthreads();
    float4 acc = make_float4(0,0,0,0);
    float sumw = 0.f;
    #pragma unroll 2
    for(int e = 0; e < deg; e++){
        float w = sw[h][e];
        sumw += w;
        float4 xv = ((const float4*)(xp + (size_t)ss[e]*F3))[h*128 + q];
        acc.x += w*xv.x; acc.y += w*xv.y; acc.z += w*xv.z; acc.w += w*xv.w;
    }
    float rd = 1.f/fmaxf(sumw, 1e-16f);
    int j0 = h*512 + q*4;
    float4 bv = ((const float4*)bias)[h*128 + q];
    float v0 = acc.x*rd + bv.x, v1 = acc.y*rd + bv.y;
    float v2 = acc.z*rd + bv.z, v3 = acc.w*rd + bv.w;
    __nv_bfloat16 h0,l0,h1,l1,h2,l2,h3,l3;
    split2(v0,h0,l0); split2(v1,h1,l1); split2(v2,h2,l2); split2(v3,h3,l3);
    uint64_t hiP = (uint64_t)bfbits(h0) | ((uint64_t)bfbits(h1)<<16)
                 | ((uint64_t)bfbits(h2)<<32) | ((uint64_t)bfbits(h3)<<48);
    uint64_t loP = (uint64_t)bfbits(l0) | ((uint64_t)bfbits(l1)<<16)
                 | ((uint64_t)bfbits(l2)<<32) | ((uint64_t)bfbits(l3)<<48);
    char* Ob = (char*)out;
    *(uint64_t*)(Ob + swaddr(n, j0,        3*F3)) = hiP;
    *(uint64_t*)(Ob + swaddr(n, F3 + j0,   3*F3)) = loP;
    *(uint64_t*)(Ob + swaddr(n, 2*F3 + j0, 3*F3)) = hiP;
}

__global__ void k_bnstats(const float* __restrict__ h, float* __restrict__ bsum,
                          float* __restrict__ bsq, int M){
    int t = threadIdx.x;
    int r0 = blockIdx.x*64;
    float s0=0,q0=0,s1=0,q1=0;
    int rend = min(r0+64, M);
    for(int r = r0; r < rend; r++){
        float v0 = h[(size_t)r*EMB + t], v1 = h[(size_t)r*EMB + t + 256];
        s0 += v0; q0 += v0*v0; s1 += v1; q1 += v1*v1;
    }
    atomicAdd(&bsum[t], s0);     atomicAdd(&bsq[t], q0);
    atomicAdd(&bsum[t+256], s1); atomicAdd(&bsq[t+256], q1);
}

__global__ void k_rnorm2(const float* __restrict__ p1, const float* __restrict__ p2){
    __shared__ float red[512];
    const float* p = blockIdx.x ? p2 : p1;
    int t = threadIdx.x;
    float v = p[t]; red[t] = v*v; __syncthreads();
    for(int o = 256; o; o >>= 1){ if(t < o) red[t] += red[t+o]; __syncthreads(); }
    if(!t) d_rnorm[blockIdx.x] = rsqrtf(red[0]);
}

__global__ void k_bnapply(const float* __restrict__ h, const float* __restrict__ g,
                          const float* __restrict__ be, const float* __restrict__ p,
                          const float* __restrict__ bsum, const float* __restrict__ bsq,
                          float* __restrict__ y, float* __restrict__ score, int M, int rsel){
    int row = blockIdx.x, t = threadIdx.x;
    float invM = 1.f/(float)M;
    float dot = 0.f;
    #pragma unroll
    for(int u = 0; u < 2; u++){
        int c = t + u*256;
        float m = bsum[c]*invM;
        float v = bsq[c]*invM - m*m;
        float yy = (h[(size_t)row*EMB + c] - m)*rsqrtf(v + 1e-5f)*g[c] + be[c];
        y[(size_t)row*EMB + c] = yy;
        dot += yy*p[c];
    }
    __shared__ float red[256];
    red[t] = dot; __syncthreads();
    for(int o = 128; o; o >>= 1){ if(t < o) red[t] += red[t+o]; __syncthreads(); }
    if(!t) score[row] = tanhf(red[0]*d_rnorm[rsel]);
}

/* top-k sort: writes perm indices, sorted scores, and (optional) mapping */
__global__ void k_topk_sort(const float* __restrict__ score, int* map,
                            int* __restrict__ prm, float* __restrict__ psc,
                            int n_per, int keep){
    int b = blockIdx.x, t = threadIdx.x;      /* 512 */
    __shared__ float sk[512]; __shared__ int si[512];
    sk[t] = (t < n_per) ? score[b*n_per + t] : -3.0e38f;
    si[t] = t;
    __syncthreads();
    for(int k = 2; k <= 512; k <<= 1)
        for(int j = k>>1; j > 0; j >>= 1){
            int x = t ^ j;
            if(x > t){
                bool up = ((t & k) == 0);
                float a = sk[t], c = sk[x];
                bool sw = up ? (a < c) : (a > c);
                if(sw){ sk[t]=c; sk[x]=a; int ti=si[t]; si[t]=si[x]; si[x]=ti; }
            }
            __syncthreads();
        }
    if(map){
        if(t < n_per) map[b*n_per + t] = -1;
        __syncthreads();
        if(t < keep) map[b*n_per + si[t]] = b*keep + t;
    }
    prm[b*512 + t] = si[t];
    psc[b*512 + t] = sk[t];
}

/* gather: grid (NB, nch). 8 rows/CTA: scale, split store, pool partials */
__global__ void k_gather(const float* __restrict__ y, const int* __restrict__ prm,
                         const float* __restrict__ psc, __nv_bfloat16* split,
                         float* __restrict__ pm, float* __restrict__ ps,
                         int n_per, int keep, int nch){
    int b = blockIdx.x, c = blockIdx.y, t = threadIdx.x;   /* 512 */
    char* Sb = (char*)split;
    float mx = -3.0e38f, sm = 0.f;
    #pragma unroll
    for(int rr = 0; rr < 8; rr++){
        int r = c*8 + rr;
        if(r < keep){
            int node = b*n_per + prm[b*512 + r];
            float s = psc[b*512 + r];
            float v = y[(size_t)node*EMB + t]*s;
            mx = fmaxf(mx, v); sm += v;
            if(split){
                int row = b*keep + r;
                __nv_bfloat16 hi, lo; split2(v, hi, lo);
                *(__nv_bfloat16*)(Sb + swaddr(row, t,         3*EMB)) = hi;
                *(__nv_bfloat16*)(Sb + swaddr(row, EMB + t,   3*EMB)) = lo;
                *(__nv_bfloat16*)(Sb + swaddr(row, 2*EMB + t, 3*EMB)) = hi;
            }
        }
    }
    pm[((size_t)b*nch + c)*512 + t] = mx;
    ps[((size_t)b*nch + c)*512 + t] = sm;
}

__global__ void k_relabel(const int* __restrict__ ei){
    int i = blockIdx.x*blockDim.x + threadIdx.x;
    if(i >= NEDGE) return;
    d_s2[i] = d_map1[ei[i]];
    d_t2[i] = d_map1[ei[NEDGE + i]];
}

/* fused head: pool finalize (both layers) + MLP1 + MLP2. one block per graph */
__global__ __launch_bounds__(512)
void k_head(const float* __restrict__ Wl1, const float* __restrict__ bl1,
            const float* __restrict__ Wl2, const float* __restrict__ bl2,
            float* __restrict__ out){
    int b = blockIdx.x, t = threadIdx.x;      /* 512 */
    __shared__ float xg[1024];
    __shared__ float tt[512];
    float mx1 = -3.0e38f, sm1 = 0.f;
    for(int c = 0; c < NCH1; c++){
        mx1 = fmaxf(mx1, d_pm1[((size_t)b*NCH1 + c)*512 + t]);
        sm1 += d_ps1[((size_t)b*NCH1 + c)*512 + t];
    }
    float mx2 = -3.0e38f, sm2 = 0.f;
    for(int c = 0; c < NCH2; c++){
        mx2 = fmaxf(mx2, d_pm2[((size_t)b*NCH2 + c)*512 + t]);
        sm2 += d_ps2[((size_t)b*NCH2 + c)*512 + t];
    }
    xg[t]       = mx1 + mx2;
    xg[512 + t] = sm1/(float)KP1 + sm2/(float)KP2;
    __syncthreads();
    float s = bl1[t];
    for(int k = 0; k < 1024; k++) s += xg[k]*Wl1[k*512 + t];
    tt[t] = fmaxf(s, 0.f);
    __syncthreads();
    if(t < 256){
        float o = bl2[t];
        for(int k = 0; k < 512; k++) o += tt[k]*Wl2[k*256 + t];
        out[b*256 + t] = o;
    }
}

/* -------------------------------- host ------------------------------------ */
#define GETP(T, v, sym_) T* v; { void* _p; cudaGetSymbolAddress(&_p, sym_); v = (T*)_p; }

extern "C" void kernel_launch(void* const* d_in, const int* in_sizes, int n_in,
                              void* d_out, int out_size){
    (void)in_sizes; (void)n_in; (void)out_size;
    const float* x   = (const float*)d_in[0];
    const int*   ei  = (const int*)  d_in[1];
    const float* W1  = (const float*)d_in[2];
    const float* as1 = (const float*)d_in[3];
    const float* ad1 = (const float*)d_in[4];
    const float* bc1 = (const float*)d_in[5];
    const float* Wh1 = (const float*)d_in[6];
    const float* bh1 = (const float*)d_in[7];
    const float* g1  = (const float*)d_in[8];
    const float* be1 = (const float*)d_in[9];
    const float* p1  = (const float*)d_in[10];
    const float* W2  = (const float*)d_in[11];
    const float* as2 = (const float*)d_in[12];
    const float* ad2 = (const float*)d_in[13];
    const float* bc2 = (const float*)d_in[14];
    const float* Wh2 = (const float*)d_in[15];
    const float* bh2 = (const float*)d_in[16];
    const float* g2  = (const float*)d_in[17];
    const float* be2 = (const float*)d_in[18];
    const float* p2  = (const float*)d_in[19];
    const float* Wl1 = (const float*)d_in[20];
    const float* bl1 = (const float*)d_in[21];
    const float* Wl2 = (const float*)d_in[22];
    const float* bl2 = (const float*)d_in[23];

    GETP(float, xp1, d_xp1)   GETP(float, asn1, d_asn1) GETP(float, adn1, d_adn1)
    GETP(unsigned, emax1, d_emax1)
    GETP(int, cnt1, d_cnt1)   GETP(int, eid1, d_eid1)   GETP(float, h1, d_h1)
    GETP(float, y1, d_y1)     GETP(float, sc1, d_sc1)   GETP(int, map1, d_map1)
    GETP(int, s2, d_s2)       GETP(int, t2, d_t2)
    GETP(float, xp2, d_xp2)   GETP(float, asn2, d_asn2) GETP(float, adn2, d_adn2)
    GETP(unsigned, emax2, d_emax2)
    GETP(int, cnt2, d_cnt2)   GETP(int, eid2, d_eid2)   GETP(float, h2, d_h2)
    GETP(float, y2, d_y2)     GETP(float, sc2, d_sc2)
    GETP(float, bsum1, d_bsum1) GETP(float, bsq1, d_bsq1)
    GETP(float, bsum2, d_bsum2) GETP(float, bsq2, d_bsq2)
    GETP(int, prm, d_prm)     GETP(float, psc, d_psc)
    GETP(float, pm1, d_pm1)   GETP(float, ps1, d_ps1)
    GETP(float, pm2, d_pm2)   GETP(float, ps2, d_ps2)
    GETP(__nv_bfloat16, a16, d_a16)
    GETP(__nv_bfloat16, bw1, d_bw1) GETP(__nv_bfloat16, bw2, d_bw2) GETP(__nv_bfloat16, bw3, d_bw3)

    cudaFuncSetAttribute(k_tgemm<0>, cudaFuncAttributeMaxDynamicSharedMemorySize, TG_SMEM);
    cudaFuncSetAttribute(k_tgemm<1>, cudaFuncAttributeMaxDynamicSharedMemorySize, TG_SMEM);

    dim3 tb(32,8);

    /* idx 0 */ k_zero_all<<<CDIV(NN1*3,256),256>>>();
    /* idx 1 */ k_xw1att<<<NN1,256>>>(x, W1, as1, ad1);
    /* idx 2 */ k_edge_pass1<<<CDIV(E1TOT,256),256>>>(ei, ei+NEDGE, cnt1, eid1, emax1, asn1, adn1, NN1);
    /* idx 3: ncu capture -> k_agg */
    k_agg<<<NN1,384>>>(cnt1, eid1, ei, xp1, asn1, adn1, emax1, bc1, a16);

    k_split_bT<<<dim3(F3/32,512/32),tb>>>(Wh1, bw1, F3, 512);
    k_tgemm<1><<<dim3(4, NN1/128),TG_THREADS,TG_SMEM>>>(a16, bw1, bh1, h1, NN1, 512, 3*F3);

    k_split_bT<<<dim3(EMB/32,F3/32),tb>>>(W2, bw2, EMB, F3);
    k_split_bT<<<dim3(F3/32,512/32),tb>>>(Wh2, bw3, F3, 512);
    k_rnorm2<<<2,512>>>(p1, p2);

    k_bnstats<<<CDIV(NN1,64),256>>>(h1, bsum1, bsq1, NN1);
    k_bnapply<<<NN1,256>>>(h1, g1, be1, p1, bsum1, bsq1, y1, sc1, NN1, 0);
    k_topk_sort<<<NBATCH,512>>>(sc1, map1, prm, psc, 512, KP1);
    k_gather<<<dim3(NBATCH,NCH1),512>>>(y1, prm, psc, a16, pm1, ps1, 512, KP1, NCH1);
    k_relabel<<<CDIV(NEDGE,256),256>>>(ei);

    /* ---- layer 2 ---- */
    k_tgemm<0><<<dim3(F3/128, CDIV(NN2,128)),TG_THREADS,TG_SMEM>>>(a16, bw2, (const float*)nullptr, xp2, NN2, F3, 3*EMB);

    k_attdot<<<CDIV(NN2*3*32,256),256>>>(xp2, as2, ad2, asn2, adn2, NN2);
    k_edge_pass1<<<CDIV(E2TOT,256),256>>>(s2, t2, cnt2, eid2, emax2, asn2, adn2, NN2);
    k_agg<<<NN2,384>>>(cnt2, eid2, s2, xp2, asn2, adn2, emax2, bc2, a16);

    k_tgemm<1><<<dim3(4, CDIV(NN2,128)),TG_THREADS,TG_SMEM>>>(a16, bw3, bh2, h2, NN2, 512, 3*F3);

    k_bnstats<<<CDIV(NN2,64),256>>>(h2, bsum2, bsq2, NN2);
    k_bnapply<<<NN2,256>>>(h2, g2, be2, p2, bsum2, bsq2, y2, sc2, NN2, 1);
    k_topk_sort<<<NBATCH,512>>>(sc2, (int*)nullptr, prm, psc, KP1, KP2);
    k_gather<<<dim3(NBATCH,NCH2),512>>>(y2, prm, psc, (__nv_bfloat16*)nullptr, pm2, ps2, KP1, KP2, NCH2);

    /* ---- fused head ---- */
    k_head<<<NBATCH,512>>>(Wl1, bl1, Wl2, bl2, (float*)d_out);
}